// round 2
// baseline (speedup 1.0000x reference)
#include <cuda_runtime.h>
#include <cuda_bf16.h>
#include <math.h>

#define B_  2
#define T_  2048
#define C_  1024
#define H_  16
#define D_  64
#define CH_ 512
#define M_  (B_ * T_)   // 4096 token rows

// ---------------- scratch (static device allocations; no cudaMalloc) ----------------
__device__ float g_hid_ch[M_ * CH_];     // importance hidden
__device__ float g_xi[M_ * C_];          // gated input
__device__ float g_hid_c[M_ * C_];       // reasoning hidden
__device__ float g_reasoned[M_ * C_];
__device__ float g_q[M_ * C_];
__device__ float g_k[M_ * C_];
__device__ float g_v[M_ * C_];
__device__ float g_attn[M_ * C_];        // attention output in [B,T,C] layout
__device__ float g_proj[M_ * C_];        // o-projection output
__device__ float g_meanr[B_ * C_];
__device__ float g_temp[B_ * H_];

// ---------------- reductions ----------------
__device__ __forceinline__ float block_reduce_sum(float v, float* sbuf) {
    int lane = threadIdx.x & 31, wid = threadIdx.x >> 5;
    #pragma unroll
    for (int o = 16; o > 0; o >>= 1) v += __shfl_xor_sync(0xffffffffu, v, o);
    if (lane == 0) sbuf[wid] = v;
    __syncthreads();
    int nw = blockDim.x >> 5;
    float r = (threadIdx.x < nw) ? sbuf[threadIdx.x] : 0.f;
    if (wid == 0) {
        #pragma unroll
        for (int o = 16; o > 0; o >>= 1) r += __shfl_xor_sync(0xffffffffu, r, o);
        if (lane == 0) sbuf[32] = r;
    }
    __syncthreads();
    float out = sbuf[32];
    __syncthreads();
    return out;
}

__device__ __forceinline__ float block_reduce_max(float v, float* sbuf) {
    int lane = threadIdx.x & 31, wid = threadIdx.x >> 5;
    #pragma unroll
    for (int o = 16; o > 0; o >>= 1) v = fmaxf(v, __shfl_xor_sync(0xffffffffu, v, o));
    if (lane == 0) sbuf[wid] = v;
    __syncthreads();
    int nw = blockDim.x >> 5;
    float r = (threadIdx.x < nw) ? sbuf[threadIdx.x] : -INFINITY;
    if (wid == 0) {
        #pragma unroll
        for (int o = 16; o > 0; o >>= 1) r = fmaxf(r, __shfl_xor_sync(0xffffffffu, r, o));
        if (lane == 0) sbuf[32] = r;
    }
    __syncthreads();
    float out = sbuf[32];
    __syncthreads();
    return out;
}

__device__ __forceinline__ float gelu_exact(float z) {
    return 0.5f * z * (1.f + erff(z * 0.70710678118654752f));
}

// ---------------- tiled SGEMM: C[M,N] = A[M,K] @ W[K,N] + bias[N] ----------------
// BM=BN=64, BK=16, 256 threads, 4x4 microtile. Requires M%64==0, N%64==0, K%16==0.
#define BM 64
#define BN 64
#define BK 16
__global__ __launch_bounds__(256) void gemm_bias_kernel(
    const float* __restrict__ A, const float* __restrict__ W,
    const float* __restrict__ bias, float* __restrict__ C,
    int M, int N, int K)
{
    __shared__ float As[BK][BM];
    __shared__ float Bs[BK][BN];
    int tid = threadIdx.x;
    int blockRow = blockIdx.y * BM;
    int blockCol = blockIdx.x * BN;
    int tr = (tid >> 4) << 2;   // 0..60
    int tc = (tid & 15) << 2;   // 0..60
    float acc[4][4] = {};

    for (int k0 = 0; k0 < K; k0 += BK) {
        #pragma unroll
        for (int i = 0; i < 4; i++) {
            int idx = tid + i * 256;               // 0..1023
            int m = idx >> 4, k = idx & 15;        // BM x BK
            As[k][m] = A[(size_t)(blockRow + m) * K + k0 + k];
        }
        #pragma unroll
        for (int i = 0; i < 4; i++) {
            int idx = tid + i * 256;
            int k = idx >> 6, n = idx & 63;        // BK x BN
            Bs[k][n] = W[(size_t)(k0 + k) * N + blockCol + n];
        }
        __syncthreads();
        #pragma unroll
        for (int k = 0; k < BK; k++) {
            float a[4], b[4];
            #pragma unroll
            for (int i = 0; i < 4; i++) a[i] = As[k][tr + i];
            #pragma unroll
            for (int j = 0; j < 4; j++) b[j] = Bs[k][tc + j];
            #pragma unroll
            for (int i = 0; i < 4; i++)
                #pragma unroll
                for (int j = 0; j < 4; j++)
                    acc[i][j] = fmaf(a[i], b[j], acc[i][j]);
        }
        __syncthreads();
    }
    #pragma unroll
    for (int i = 0; i < 4; i++) {
        int m = blockRow + tr + i;
        #pragma unroll
        for (int j = 0; j < 4; j++) {
            int n = blockCol + tc + j;
            C[(size_t)m * N + n] = acc[i][j] + bias[n];
        }
    }
}

// ---------------- in-place LayerNorm + exact GELU, one block per row ----------------
__global__ __launch_bounds__(256) void ln_gelu_kernel(
    float* __restrict__ buf, const float* __restrict__ g,
    const float* __restrict__ beta, int N)
{
    __shared__ float red[33];
    float* x = buf + (size_t)blockIdx.x * N;
    float s = 0.f;
    for (int i = threadIdx.x; i < N; i += blockDim.x) s += x[i];
    float m = block_reduce_sum(s, red) / (float)N;
    float v = 0.f;
    for (int i = threadIdx.x; i < N; i += blockDim.x) { float d = x[i] - m; v += d * d; }
    v = block_reduce_sum(v, red) / (float)N;
    float rstd = rsqrtf(v + 1e-5f);
    for (int i = threadIdx.x; i < N; i += blockDim.x) {
        float z = (x[i] - m) * rstd * g[i] + beta[i];
        x[i] = gelu_exact(z);
    }
}

// ---------------- importance gate: dot(512) -> sigmoid -> clamp -> xi = x*imp ----------------
__global__ __launch_bounds__(256) void gate_kernel(
    const float* __restrict__ hln, const float* __restrict__ w2,
    const float* __restrict__ b2, const float* __restrict__ x,
    float* __restrict__ xi)
{
    __shared__ float red[33];
    int row = blockIdx.x;
    const float* hr = hln + (size_t)row * CH_;
    float s = 0.f;
    for (int i = threadIdx.x; i < CH_; i += blockDim.x) s += hr[i] * w2[i];
    s = block_reduce_sum(s, red);
    float imp = fmaxf(1.f / (1.f + expf(-(s + b2[0]))), 1e-6f);
    const float* xr = x + (size_t)row * C_;
    float* xir = xi + (size_t)row * C_;
    for (int i = threadIdx.x; i < C_; i += blockDim.x) xir[i] = xr[i] * imp;
}

// ---------------- mean over T: reasoned [B,T,C] -> [B,C] ----------------
__global__ void mean_t_kernel(const float* __restrict__ r, float* __restrict__ out) {
    int idx = blockIdx.x * blockDim.x + threadIdx.x;  // 0..B*C-1
    if (idx >= B_ * C_) return;
    int b = idx / C_, c = idx % C_;
    float s = 0.f;
    for (int t = 0; t < T_; t++) s += r[((size_t)b * T_ + t) * C_ + c];
    out[idx] = s * (1.f / (float)T_);
}

// ---------------- temperature net: [B,C] -> Linear -> LN -> GELU -> Linear -> softplus+0.5 ----------------
__global__ __launch_bounds__(512) void temp_kernel(
    const float* __restrict__ meanr, const float* __restrict__ w1,
    const float* __restrict__ b1, const float* __restrict__ g,
    const float* __restrict__ beta, const float* __restrict__ w2,
    const float* __restrict__ b2, float* __restrict__ temp)
{
    __shared__ float h[CH_];
    __shared__ float red[33];
    int b = blockIdx.x, tid = threadIdx.x;
    const float* mr = meanr + (size_t)b * C_;
    float acc = b1[tid];
    for (int k = 0; k < C_; k++) acc = fmaf(mr[k], w1[(size_t)k * CH_ + tid], acc);
    float m = block_reduce_sum(acc, red) / (float)CH_;
    float d = acc - m;
    float var = block_reduce_sum(d * d, red) / (float)CH_;
    float z = d * rsqrtf(var + 1e-5f) * g[tid] + beta[tid];
    h[tid] = gelu_exact(z);
    __syncthreads();
    if (tid < H_) {
        float a = b2[tid];
        for (int i = 0; i < CH_; i++) a = fmaf(h[i], w2[(size_t)i * H_ + tid], a);
        // stable softplus
        float sp = fmaxf(a, 0.f) + log1pf(expf(-fabsf(a)));
        temp[b * H_ + tid] = sp + 0.5f;
    }
}

// ---------------- attention: one block per (b,h,q), two-pass softmax in smem ----------------
__global__ __launch_bounds__(128) void attn_kernel(
    const float* __restrict__ Q, const float* __restrict__ K,
    const float* __restrict__ V, const int* __restrict__ mask,
    const float* __restrict__ temp, float* __restrict__ O)
{
    int qi = blockIdx.x, h = blockIdx.y, b = blockIdx.z;
    int tid = threadIdx.x;
    __shared__ float qs[D_];
    __shared__ float sc[T_];
    __shared__ float red[33];
    __shared__ float partial[128];

    const float* qrow = Q + ((size_t)b * T_ + qi) * C_ + h * D_;
    if (tid < D_) qs[tid] = qrow[tid];
    __syncthreads();

    float sc_scale = temp[b * H_ + h] * 0.125f;   // temp * 1/sqrt(64)
    const int* mrow = mask + ((size_t)b * T_ + qi) * T_;
    const float4* q4 = (const float4*)qs;

    float lmax = -INFINITY;
    for (int j = tid; j < T_; j += 128) {
        float s;
        if (mrow[j] == 0) {
            s = -INFINITY;
        } else {
            const float4* kr = (const float4*)(K + ((size_t)b * T_ + j) * C_ + h * D_);
            float acc = 0.f;
            #pragma unroll
            for (int d = 0; d < D_ / 4; d++) {
                float4 kk = kr[d]; float4 qq = q4[d];
                acc = fmaf(kk.x, qq.x, acc);
                acc = fmaf(kk.y, qq.y, acc);
                acc = fmaf(kk.z, qq.z, acc);
                acc = fmaf(kk.w, qq.w, acc);
            }
            s = acc * sc_scale;
        }
        sc[j] = s;
        lmax = fmaxf(lmax, s);
    }
    float mx = block_reduce_max(lmax, red);
    float lsum = 0.f;
    for (int j = tid; j < T_; j += 128) {
        float p = expf(sc[j] - mx);
        sc[j] = p;
        lsum += p;
    }
    float inv = 1.f / block_reduce_sum(lsum, red);

    int d = tid & (D_ - 1), half = tid >> 6;   // 2 key-halves x 64 dims
    float acc = 0.f;
    int j0 = half * (T_ / 2), j1 = j0 + T_ / 2;
    for (int j = j0; j < j1; j++)
        acc = fmaf(sc[j], V[((size_t)b * T_ + j) * C_ + h * D_ + d], acc);
    partial[tid] = acc;
    __syncthreads();
    if (tid < D_)
        O[((size_t)b * T_ + qi) * C_ + h * D_ + tid] =
            (partial[tid] + partial[tid + D_]) * inv;
}

// ---------------- residual + final LayerNorm -> d_out ----------------
__global__ __launch_bounds__(256) void ln_res_kernel(
    const float* __restrict__ x, const float* __restrict__ y,
    const float* __restrict__ g, const float* __restrict__ beta,
    float* __restrict__ out)
{
    __shared__ float red[33];
    int row = blockIdx.x;
    const float* xr = x + (size_t)row * C_;
    const float* yr = y + (size_t)row * C_;
    float* orow = out + (size_t)row * C_;
    float s = 0.f;
    for (int i = threadIdx.x; i < C_; i += blockDim.x) s += xr[i] + yr[i];
    float m = block_reduce_sum(s, red) / (float)C_;
    float v = 0.f;
    for (int i = threadIdx.x; i < C_; i += blockDim.x) {
        float d = xr[i] + yr[i] - m; v += d * d;
    }
    v = block_reduce_sum(v, red) / (float)C_;
    float rstd = rsqrtf(v + 1e-5f);
    for (int i = threadIdx.x; i < C_; i += blockDim.x) {
        float z = (xr[i] + yr[i] - m) * rstd;
        orow[i] = z * g[i] + beta[i];
    }
}

// ---------------- host launcher ----------------
static float* devptr(const void* sym) {
    void* p = nullptr;
    cudaGetSymbolAddress(&p, sym);
    return (float*)p;
}

extern "C" void kernel_launch(void* const* d_in, const int* in_sizes, int n_in,
                              void* d_out, int out_size) {
    const float* x        = (const float*)d_in[0];
    const int*   mask     = (const int*)  d_in[1];
    const float* imp_w1   = (const float*)d_in[2];
    const float* imp_b1   = (const float*)d_in[3];
    const float* imp_g    = (const float*)d_in[4];
    const float* imp_beta = (const float*)d_in[5];
    const float* imp_w2   = (const float*)d_in[6];
    const float* imp_b2   = (const float*)d_in[7];
    const float* rsn_w1   = (const float*)d_in[8];
    const float* rsn_b1   = (const float*)d_in[9];
    const float* rsn_g    = (const float*)d_in[10];
    const float* rsn_beta = (const float*)d_in[11];
    const float* rsn_w2   = (const float*)d_in[12];
    const float* rsn_b2   = (const float*)d_in[13];
    const float* q_w      = (const float*)d_in[14];
    const float* q_b      = (const float*)d_in[15];
    const float* k_w      = (const float*)d_in[16];
    const float* k_b      = (const float*)d_in[17];
    const float* v_w      = (const float*)d_in[18];
    const float* v_b      = (const float*)d_in[19];
    const float* o_w      = (const float*)d_in[20];
    const float* o_b      = (const float*)d_in[21];
    const float* tmp_w1   = (const float*)d_in[22];
    const float* tmp_b1   = (const float*)d_in[23];
    const float* tmp_g    = (const float*)d_in[24];
    const float* tmp_beta = (const float*)d_in[25];
    const float* tmp_w2   = (const float*)d_in[26];
    const float* tmp_b2   = (const float*)d_in[27];
    const float* norm_g   = (const float*)d_in[28];
    const float* norm_b   = (const float*)d_in[29];
    float* out = (float*)d_out;

    float* hid_ch   = devptr(g_hid_ch);
    float* xi       = devptr(g_xi);
    float* hid_c    = devptr(g_hid_c);
    float* reasoned = devptr(g_reasoned);
    float* q        = devptr(g_q);
    float* k        = devptr(g_k);
    float* v        = devptr(g_v);
    float* attn     = devptr(g_attn);
    float* proj     = devptr(g_proj);
    float* meanr    = devptr(g_meanr);
    float* temp     = devptr(g_temp);

    dim3 gemm_ch(CH_ / BN, M_ / BM);
    dim3 gemm_c (C_  / BN, M_ / BM);

    // importance net
    gemm_bias_kernel<<<gemm_ch, 256>>>(x, imp_w1, imp_b1, hid_ch, M_, CH_, C_);
    ln_gelu_kernel<<<M_, 256>>>(hid_ch, imp_g, imp_beta, CH_);
    gate_kernel<<<M_, 256>>>(hid_ch, imp_w2, imp_b2, x, xi);

    // reasoning net
    gemm_bias_kernel<<<gemm_c, 256>>>(xi, rsn_w1, rsn_b1, hid_c, M_, C_, C_);
    ln_gelu_kernel<<<M_, 256>>>(hid_c, rsn_g, rsn_beta, C_);
    gemm_bias_kernel<<<gemm_c, 256>>>(hid_c, rsn_w2, rsn_b2, reasoned, M_, C_, C_);

    // projections
    gemm_bias_kernel<<<gemm_c, 256>>>(reasoned, q_w, q_b, q, M_, C_, C_);
    gemm_bias_kernel<<<gemm_c, 256>>>(xi, k_w, k_b, k, M_, C_, C_);
    gemm_bias_kernel<<<gemm_c, 256>>>(x, v_w, v_b, v, M_, C_, C_);

    // temperature
    mean_t_kernel<<<(B_ * C_ + 255) / 256, 256>>>(reasoned, meanr);
    temp_kernel<<<B_, 512>>>(meanr, tmp_w1, tmp_b1, tmp_g, tmp_beta, tmp_w2, tmp_b2, temp);

    // attention
    attn_kernel<<<dim3(T_, H_, B_), 128>>>(q, k, v, mask, temp, attn);

    // output projection + residual LN
    gemm_bias_kernel<<<gemm_c, 256>>>(attn, o_w, o_b, proj, M_, C_, C_);
    ln_res_kernel<<<M_, 256>>>(x, proj, norm_g, norm_b, out);
}

// round 3
// speedup vs baseline: 3.5959x; 3.5959x over previous
#include <cuda_runtime.h>
#include <cuda_bf16.h>
#include <math.h>

#define B_  2
#define T_  2048
#define C_  1024
#define H_  16
#define D_  64
#define CH_ 512
#define M_  (B_ * T_)   // 4096 token rows

// ---------------- scratch (static device allocations; no cudaMalloc) ----------------
__device__ float g_hid_ch[M_ * CH_];     // importance hidden
__device__ float g_xi[M_ * C_];          // gated input
__device__ float g_hid_c[M_ * C_];       // reasoning hidden
__device__ float g_reasoned[M_ * C_];
__device__ float g_q[M_ * C_];
__device__ float g_k[M_ * C_];
__device__ float g_v[M_ * C_];
__device__ float g_attn[M_ * C_];        // attention output in [B,T,C] layout
__device__ float g_proj[M_ * C_];        // o-projection output
__device__ float g_meanr[B_ * C_];
__device__ float g_temp[B_ * H_];

// ---------------- reductions ----------------
__device__ __forceinline__ float block_reduce_sum(float v, float* sbuf) {
    int lane = threadIdx.x & 31, wid = threadIdx.x >> 5;
    #pragma unroll
    for (int o = 16; o > 0; o >>= 1) v += __shfl_xor_sync(0xffffffffu, v, o);
    if (lane == 0) sbuf[wid] = v;
    __syncthreads();
    int nw = blockDim.x >> 5;
    float r = (threadIdx.x < nw) ? sbuf[threadIdx.x] : 0.f;
    if (wid == 0) {
        #pragma unroll
        for (int o = 16; o > 0; o >>= 1) r += __shfl_xor_sync(0xffffffffu, r, o);
        if (lane == 0) sbuf[32] = r;
    }
    __syncthreads();
    float out = sbuf[32];
    __syncthreads();
    return out;
}

__device__ __forceinline__ float gelu_exact(float z) {
    return 0.5f * z * (1.f + erff(z * 0.70710678118654752f));
}

// ---------------- tiled SGEMM v2: C[M,N] = A[M,K] @ W[K,N] + bias[N] ----------------
// 128x128x8 tile, 256 threads, 8x8 microtile. Requires M%128==0, N%128==0, K%8==0.
#define GBM 128
#define GBN 128
#define GBK 8
__global__ __launch_bounds__(256, 2) void gemm_bias_kernel(
    const float* __restrict__ A, const float* __restrict__ W,
    const float* __restrict__ bias, float* __restrict__ Cout,
    int M, int N, int K)
{
    __shared__ float As[GBK][GBM];
    __shared__ float Bs[GBK][GBN];
    int tid = threadIdx.x;
    int brow = blockIdx.y * GBM;
    int bcol = blockIdx.x * GBN;
    int ty = tid >> 4, tx = tid & 15;
    int i0 = ty << 3, j0 = tx << 3;

    // load-index precompute
    int lr = tid >> 1;            // A row within tile 0..127
    int lk = (tid & 1) << 2;      // A k offset 0 or 4
    int bk = tid >> 5;            // B k row 0..7
    int bn = (tid & 31) << 2;     // B col 0..124

    const float* Aptr = A + (size_t)(brow + lr) * K + lk;
    const float* Wptr = W + (size_t)bk * N + bcol + bn;

    float acc[8][8] = {};

    for (int k0 = 0; k0 < K; k0 += GBK) {
        float4 av = *(const float4*)(Aptr + k0);
        float4 bv = *(const float4*)(Wptr + (size_t)k0 * N);
        As[lk + 0][lr] = av.x;
        As[lk + 1][lr] = av.y;
        As[lk + 2][lr] = av.z;
        As[lk + 3][lr] = av.w;
        *(float4*)&Bs[bk][bn] = bv;
        __syncthreads();

        #pragma unroll
        for (int k = 0; k < GBK; k++) {
            float a[8], b[8];
            *(float4*)(a)     = *(const float4*)&As[k][i0];
            *(float4*)(a + 4) = *(const float4*)&As[k][i0 + 4];
            *(float4*)(b)     = *(const float4*)&Bs[k][j0];
            *(float4*)(b + 4) = *(const float4*)&Bs[k][j0 + 4];
            #pragma unroll
            for (int i = 0; i < 8; i++)
                #pragma unroll
                for (int j = 0; j < 8; j++)
                    acc[i][j] = fmaf(a[i], b[j], acc[i][j]);
        }
        __syncthreads();
    }

    float bl[8];
    *(float4*)(bl)     = *(const float4*)(bias + bcol + j0);
    *(float4*)(bl + 4) = *(const float4*)(bias + bcol + j0 + 4);
    #pragma unroll
    for (int i = 0; i < 8; i++) {
        float* crow = Cout + (size_t)(brow + i0 + i) * N + bcol + j0;
        float4 o0, o1;
        o0.x = acc[i][0] + bl[0]; o0.y = acc[i][1] + bl[1];
        o0.z = acc[i][2] + bl[2]; o0.w = acc[i][3] + bl[3];
        o1.x = acc[i][4] + bl[4]; o1.y = acc[i][5] + bl[5];
        o1.z = acc[i][6] + bl[6]; o1.w = acc[i][7] + bl[7];
        *(float4*)(crow)     = o0;
        *(float4*)(crow + 4) = o1;
    }
}

// ---------------- in-place LayerNorm + exact GELU, one block per row ----------------
__global__ __launch_bounds__(256) void ln_gelu_kernel(
    float* __restrict__ buf, const float* __restrict__ g,
    const float* __restrict__ beta, int N)
{
    __shared__ float red[33];
    float* x = buf + (size_t)blockIdx.x * N;
    float s = 0.f;
    for (int i = threadIdx.x; i < N; i += blockDim.x) s += x[i];
    float m = block_reduce_sum(s, red) / (float)N;
    float v = 0.f;
    for (int i = threadIdx.x; i < N; i += blockDim.x) { float d = x[i] - m; v += d * d; }
    v = block_reduce_sum(v, red) / (float)N;
    float rstd = rsqrtf(v + 1e-5f);
    for (int i = threadIdx.x; i < N; i += blockDim.x) {
        float z = (x[i] - m) * rstd * g[i] + beta[i];
        x[i] = gelu_exact(z);
    }
}

// ---------------- importance gate ----------------
__global__ __launch_bounds__(256) void gate_kernel(
    const float* __restrict__ hln, const float* __restrict__ w2,
    const float* __restrict__ b2, const float* __restrict__ x,
    float* __restrict__ xi)
{
    __shared__ float red[33];
    int row = blockIdx.x;
    const float* hr = hln + (size_t)row * CH_;
    float s = 0.f;
    for (int i = threadIdx.x; i < CH_; i += blockDim.x) s += hr[i] * w2[i];
    s = block_reduce_sum(s, red);
    float imp = fmaxf(1.f / (1.f + expf(-(s + b2[0]))), 1e-6f);
    const float* xr = x + (size_t)row * C_;
    float* xir = xi + (size_t)row * C_;
    for (int i = threadIdx.x; i < C_; i += blockDim.x) xir[i] = xr[i] * imp;
}

// ---------------- mean over T ----------------
__global__ void mean_t_kernel(const float* __restrict__ r, float* __restrict__ out) {
    int idx = blockIdx.x * blockDim.x + threadIdx.x;
    if (idx >= B_ * C_) return;
    int b = idx / C_, c = idx % C_;
    float s = 0.f;
    for (int t = 0; t < T_; t++) s += r[((size_t)b * T_ + t) * C_ + c];
    out[idx] = s * (1.f / (float)T_);
}

// ---------------- temperature net ----------------
__global__ __launch_bounds__(512) void temp_kernel(
    const float* __restrict__ meanr, const float* __restrict__ w1,
    const float* __restrict__ b1, const float* __restrict__ g,
    const float* __restrict__ beta, const float* __restrict__ w2,
    const float* __restrict__ b2, float* __restrict__ temp)
{
    __shared__ float h[CH_];
    __shared__ float red[33];
    int b = blockIdx.x, tid = threadIdx.x;
    const float* mr = meanr + (size_t)b * C_;
    float acc = b1[tid];
    for (int k = 0; k < C_; k++) acc = fmaf(mr[k], w1[(size_t)k * CH_ + tid], acc);
    float m = block_reduce_sum(acc, red) / (float)CH_;
    float d = acc - m;
    float var = block_reduce_sum(d * d, red) / (float)CH_;
    float z = d * rsqrtf(var + 1e-5f) * g[tid] + beta[tid];
    h[tid] = gelu_exact(z);
    __syncthreads();
    if (tid < H_) {
        float a = b2[tid];
        for (int i = 0; i < CH_; i++) a = fmaf(h[i], w2[(size_t)i * H_ + tid], a);
        float sp = fmaxf(a, 0.f) + log1pf(expf(-fabsf(a)));
        temp[b * H_ + tid] = sp + 0.5f;
    }
}

// ---------------- flash attention: block = (b, h, 64-query tile) ----------------
// Streams K/V in 64-key tiles with online softmax. 256 threads, 4x4 microtiles.
#define AT 64
__global__ __launch_bounds__(256, 2) void attn_kernel(
    const float* __restrict__ Q, const float* __restrict__ K,
    const float* __restrict__ V, const int* __restrict__ mask,
    const float* __restrict__ temp, float* __restrict__ O)
{
    __shared__ float Qt[D_][AT];   // Q transposed: [d][i]
    __shared__ float KP[AT][AT];   // K transposed [d][j]; reused as P transposed [j][i]
    __shared__ float Vs[AT][AT];   // V direct: [j][c]

    int q0 = blockIdx.x * AT;
    int h = blockIdx.y, b = blockIdx.z;
    int tid = threadIdx.x;
    int ty = tid >> 4, tx = tid & 15;
    int i0 = ty << 2, j0 = tx << 2;

    // load Q tile transposed
    {
        int i = tid >> 2;
        int d0 = (tid & 3) << 4;
        const float* qr = Q + ((size_t)b * T_ + q0 + i) * C_ + h * D_ + d0;
        #pragma unroll
        for (int u = 0; u < 16; u += 4) {
            float4 qv = *(const float4*)(qr + u);
            Qt[d0 + u + 0][i] = qv.x;
            Qt[d0 + u + 1][i] = qv.y;
            Qt[d0 + u + 2][i] = qv.z;
            Qt[d0 + u + 3][i] = qv.w;
        }
    }

    float sct = temp[b * H_ + h] * 0.125f;   // temp / sqrt(64)

    float m_i[4], l_i[4], o_acc[4][4];
    #pragma unroll
    for (int r = 0; r < 4; r++) {
        m_i[r] = -INFINITY; l_i[r] = 0.f;
        #pragma unroll
        for (int c = 0; c < 4; c++) o_acc[r][c] = 0.f;
    }

    const float* Kb = K + (size_t)b * T_ * C_ + h * D_;
    const float* Vb = V + (size_t)b * T_ * C_ + h * D_;
    const int* mb = mask + ((size_t)b * T_ + q0) * T_;

    int lj = tid >> 2;             // KV load row 0..63
    int ld0 = (tid & 3) << 4;      // KV load dim offset

    for (int kt = 0; kt < T_; kt += AT) {
        __syncthreads();   // previous PV done; safe to overwrite KP/Vs
        {
            const float* kr = Kb + (size_t)(kt + lj) * C_ + ld0;
            const float* vr = Vb + (size_t)(kt + lj) * C_ + ld0;
            #pragma unroll
            for (int u = 0; u < 16; u += 4) {
                float4 kv = *(const float4*)(kr + u);
                KP[ld0 + u + 0][lj] = kv.x;
                KP[ld0 + u + 1][lj] = kv.y;
                KP[ld0 + u + 2][lj] = kv.z;
                KP[ld0 + u + 3][lj] = kv.w;
                *(float4*)&Vs[lj][ld0 + u] = *(const float4*)(vr + u);
            }
        }
        __syncthreads();

        // S = Q K^T (4x4 microtile)
        float s[4][4] = {};
        #pragma unroll 8
        for (int d = 0; d < D_; d++) {
            float4 a = *(const float4*)&Qt[d][i0];
            float4 bb = *(const float4*)&KP[d][j0];
            s[0][0] = fmaf(a.x, bb.x, s[0][0]); s[0][1] = fmaf(a.x, bb.y, s[0][1]);
            s[0][2] = fmaf(a.x, bb.z, s[0][2]); s[0][3] = fmaf(a.x, bb.w, s[0][3]);
            s[1][0] = fmaf(a.y, bb.x, s[1][0]); s[1][1] = fmaf(a.y, bb.y, s[1][1]);
            s[1][2] = fmaf(a.y, bb.z, s[1][2]); s[1][3] = fmaf(a.y, bb.w, s[1][3]);
            s[2][0] = fmaf(a.z, bb.x, s[2][0]); s[2][1] = fmaf(a.z, bb.y, s[2][1]);
            s[2][2] = fmaf(a.z, bb.z, s[2][2]); s[2][3] = fmaf(a.z, bb.w, s[2][3]);
            s[3][0] = fmaf(a.w, bb.x, s[3][0]); s[3][1] = fmaf(a.w, bb.y, s[3][1]);
            s[3][2] = fmaf(a.w, bb.z, s[3][2]); s[3][3] = fmaf(a.w, bb.w, s[3][3]);
        }

        // mask + temperature scale, then online softmax update
        #pragma unroll
        for (int r = 0; r < 4; r++) {
            int4 mk = *(const int4*)(mb + (size_t)(i0 + r) * T_ + kt + j0);
            s[r][0] = mk.x ? s[r][0] * sct : -INFINITY;
            s[r][1] = mk.y ? s[r][1] * sct : -INFINITY;
            s[r][2] = mk.z ? s[r][2] * sct : -INFINITY;
            s[r][3] = mk.w ? s[r][3] * sct : -INFINITY;

            float mx = fmaxf(fmaxf(s[r][0], s[r][1]), fmaxf(s[r][2], s[r][3]));
            #pragma unroll
            for (int o = 8; o > 0; o >>= 1)
                mx = fmaxf(mx, __shfl_xor_sync(0xffffffffu, mx, o, 16));
            float m_new = fmaxf(m_i[r], mx);
            float alpha = (m_new == -INFINITY) ? 0.f : expf(m_i[r] - m_new);
            float psum = 0.f;
            #pragma unroll
            for (int c = 0; c < 4; c++) {
                float p = (s[r][c] == -INFINITY) ? 0.f : expf(s[r][c] - m_new);
                s[r][c] = p;
                psum += p;
            }
            #pragma unroll
            for (int o = 8; o > 0; o >>= 1)
                psum += __shfl_xor_sync(0xffffffffu, psum, o, 16);
            l_i[r] = l_i[r] * alpha + psum;
            m_i[r] = m_new;
            #pragma unroll
            for (int c = 0; c < 4; c++) o_acc[r][c] *= alpha;
        }

        __syncthreads();   // everyone done reading K from KP
        // write P transposed into KP: KP[j][i] = P[i][j]
        #pragma unroll
        for (int r = 0; r < 4; r++)
            #pragma unroll
            for (int c = 0; c < 4; c++)
                KP[j0 + c][i0 + r] = s[r][c];
        __syncthreads();

        // O += P V
        #pragma unroll 4
        for (int j = 0; j < AT; j++) {
            float4 a = *(const float4*)&KP[j][i0];
            float4 bb = *(const float4*)&Vs[j][j0];
            o_acc[0][0] = fmaf(a.x, bb.x, o_acc[0][0]); o_acc[0][1] = fmaf(a.x, bb.y, o_acc[0][1]);
            o_acc[0][2] = fmaf(a.x, bb.z, o_acc[0][2]); o_acc[0][3] = fmaf(a.x, bb.w, o_acc[0][3]);
            o_acc[1][0] = fmaf(a.y, bb.x, o_acc[1][0]); o_acc[1][1] = fmaf(a.y, bb.y, o_acc[1][1]);
            o_acc[1][2] = fmaf(a.y, bb.z, o_acc[1][2]); o_acc[1][3] = fmaf(a.y, bb.w, o_acc[1][3]);
            o_acc[2][0] = fmaf(a.z, bb.x, o_acc[2][0]); o_acc[2][1] = fmaf(a.z, bb.y, o_acc[2][1]);
            o_acc[2][2] = fmaf(a.z, bb.z, o_acc[2][2]); o_acc[2][3] = fmaf(a.z, bb.w, o_acc[2][3]);
            o_acc[3][0] = fmaf(a.w, bb.x, o_acc[3][0]); o_acc[3][1] = fmaf(a.w, bb.y, o_acc[3][1]);
            o_acc[3][2] = fmaf(a.w, bb.z, o_acc[3][2]); o_acc[3][3] = fmaf(a.w, bb.w, o_acc[3][3]);
        }
    }

    // final normalize + write
    #pragma unroll
    for (int r = 0; r < 4; r++) {
        float inv = 1.f / l_i[r];
        float4 o;
        o.x = o_acc[r][0] * inv; o.y = o_acc[r][1] * inv;
        o.z = o_acc[r][2] * inv; o.w = o_acc[r][3] * inv;
        *(float4*)(O + ((size_t)b * T_ + q0 + i0 + r) * C_ + h * D_ + j0) = o;
    }
}

// ---------------- residual + final LayerNorm -> d_out ----------------
__global__ __launch_bounds__(256) void ln_res_kernel(
    const float* __restrict__ x, const float* __restrict__ y,
    const float* __restrict__ g, const float* __restrict__ beta,
    float* __restrict__ out)
{
    __shared__ float red[33];
    int row = blockIdx.x;
    const float* xr = x + (size_t)row * C_;
    const float* yr = y + (size_t)row * C_;
    float* orow = out + (size_t)row * C_;
    float s = 0.f;
    for (int i = threadIdx.x; i < C_; i += blockDim.x) s += xr[i] + yr[i];
    float m = block_reduce_sum(s, red) / (float)C_;
    float v = 0.f;
    for (int i = threadIdx.x; i < C_; i += blockDim.x) {
        float d = xr[i] + yr[i] - m; v += d * d;
    }
    v = block_reduce_sum(v, red) / (float)C_;
    float rstd = rsqrtf(v + 1e-5f);
    for (int i = threadIdx.x; i < C_; i += blockDim.x) {
        float z = (xr[i] + yr[i] - m) * rstd;
        orow[i] = z * g[i] + beta[i];
    }
}

// ---------------- host launcher ----------------
static float* devptr(const void* sym) {
    void* p = nullptr;
    cudaGetSymbolAddress(&p, sym);
    return (float*)p;
}

extern "C" void kernel_launch(void* const* d_in, const int* in_sizes, int n_in,
                              void* d_out, int out_size) {
    const float* x        = (const float*)d_in[0];
    const int*   mask     = (const int*)  d_in[1];
    const float* imp_w1   = (const float*)d_in[2];
    const float* imp_b1   = (const float*)d_in[3];
    const float* imp_g    = (const float*)d_in[4];
    const float* imp_beta = (const float*)d_in[5];
    const float* imp_w2   = (const float*)d_in[6];
    const float* imp_b2   = (const float*)d_in[7];
    const float* rsn_w1   = (const float*)d_in[8];
    const float* rsn_b1   = (const float*)d_in[9];
    const float* rsn_g    = (const float*)d_in[10];
    const float* rsn_beta = (const float*)d_in[11];
    const float* rsn_w2   = (const float*)d_in[12];
    const float* rsn_b2   = (const float*)d_in[13];
    const float* q_w      = (const float*)d_in[14];
    const float* q_b      = (const float*)d_in[15];
    const float* k_w      = (const float*)d_in[16];
    const float* k_b      = (const float*)d_in[17];
    const float* v_w      = (const float*)d_in[18];
    const float* v_b      = (const float*)d_in[19];
    const float* o_w      = (const float*)d_in[20];
    const float* o_b      = (const float*)d_in[21];
    const float* tmp_w1   = (const float*)d_in[22];
    const float* tmp_b1   = (const float*)d_in[23];
    const float* tmp_g    = (const float*)d_in[24];
    const float* tmp_beta = (const float*)d_in[25];
    const float* tmp_w2   = (const float*)d_in[26];
    const float* tmp_b2   = (const float*)d_in[27];
    const float* norm_g   = (const float*)d_in[28];
    const float* norm_b   = (const float*)d_in[29];
    float* out = (float*)d_out;

    float* hid_ch   = devptr(g_hid_ch);
    float* xi       = devptr(g_xi);
    float* hid_c    = devptr(g_hid_c);
    float* reasoned = devptr(g_reasoned);
    float* q        = devptr(g_q);
    float* k        = devptr(g_k);
    float* v        = devptr(g_v);
    float* attn     = devptr(g_attn);
    float* proj     = devptr(g_proj);
    float* meanr    = devptr(g_meanr);
    float* temp     = devptr(g_temp);

    dim3 gemm_ch(CH_ / GBN, M_ / GBM);   // (4, 32)
    dim3 gemm_c (C_  / GBN, M_ / GBM);   // (8, 32)

    // importance net
    gemm_bias_kernel<<<gemm_ch, 256>>>(x, imp_w1, imp_b1, hid_ch, M_, CH_, C_);
    ln_gelu_kernel<<<M_, 256>>>(hid_ch, imp_g, imp_beta, CH_);
    gate_kernel<<<M_, 256>>>(hid_ch, imp_w2, imp_b2, x, xi);

    // reasoning net
    gemm_bias_kernel<<<gemm_c, 256>>>(xi, rsn_w1, rsn_b1, hid_c, M_, C_, C_);
    ln_gelu_kernel<<<M_, 256>>>(hid_c, rsn_g, rsn_beta, C_);
    gemm_bias_kernel<<<gemm_c, 256>>>(hid_c, rsn_w2, rsn_b2, reasoned, M_, C_, C_);

    // projections
    gemm_bias_kernel<<<gemm_c, 256>>>(reasoned, q_w, q_b, q, M_, C_, C_);
    gemm_bias_kernel<<<gemm_c, 256>>>(xi, k_w, k_b, k, M_, C_, C_);
    gemm_bias_kernel<<<gemm_c, 256>>>(x, v_w, v_b, v, M_, C_, C_);

    // temperature
    mean_t_kernel<<<(B_ * C_ + 255) / 256, 256>>>(reasoned, meanr);
    temp_kernel<<<B_, 512>>>(meanr, tmp_w1, tmp_b1, tmp_g, tmp_beta, tmp_w2, tmp_b2, temp);

    // attention (flash-style)
    attn_kernel<<<dim3(T_ / AT, H_, B_), 256>>>(q, k, v, mask, temp, attn);

    // output projection + residual LN
    gemm_bias_kernel<<<gemm_c, 256>>>(attn, o_w, o_b, proj, M_, C_, C_);
    ln_res_kernel<<<M_, 256>>>(x, proj, norm_g, norm_b, out);
}